// round 16
// baseline (speedup 1.0000x reference)
#include <cuda_runtime.h>
#include <cuda_bf16.h>
#include <math.h>
#include <stdint.h>

#define B 64
#define S 20
#define H 128
#define E 300
#define V 50257
#define VP 50304   // V padded to multiple of 128
#define NTILES (VP / 128)   // 393

// ---------------- device scratch (static, no runtime alloc) ----------------
__device__ float g_h0[B * H];
__device__ float g_h1[B * H];
__device__ float g_mem[B * S * H];
__device__ float g_keys[B * S * H];
__device__ float g_egx[B * S * 2 * H];
__device__ float g_ecx[B * S * H];
__device__ float g_dgx[B * S * 2 * H];
__device__ float g_dcx[B * S * H];
__device__ float g_na[B * S * H];
// plain [n][k] bf16 hi/lo W_proj tiles (32KB per tile each)
__device__ unsigned short g_Bhi[NTILES * 16384];
__device__ unsigned short g_Blo[NTILES * 16384];

// ---------------- fast activations ----------------
__device__ __forceinline__ float tanh_fast(float x) {
    float y; asm("tanh.approx.f32 %0, %1;" : "=f"(y) : "f"(x)); return y;
}
__device__ __forceinline__ float sigmoid_fast(float x) {
    return fmaf(0.5f, tanh_fast(0.5f * x), 0.5f);
}

// ---------------- cluster helpers ----------------
__device__ __forceinline__ unsigned ctarank_() {
    unsigned r; asm("mov.u32 %0, %%cluster_ctarank;" : "=r"(r)); return r;
}
__device__ __forceinline__ void cluster_sync_() {
    asm volatile("barrier.cluster.arrive.aligned;" ::: "memory");
    asm volatile("barrier.cluster.wait.aligned;" ::: "memory");
}
__device__ __forceinline__ void st_peer(float* p, unsigned peer, float v) {
    unsigned la = (unsigned)__cvta_generic_to_shared(p);
    unsigned ra;
    asm("mapa.shared::cluster.u32 %0, %1, %2;" : "=r"(ra) : "r"(la), "r"(peer));
    asm volatile("st.shared::cluster.f32 [%0], %1;" :: "r"(ra), "f"(v));
}

// ---------------- warp-level bf16 MMA (sm_80+ HMMA; works on plain sm_103) ----------------
__device__ __forceinline__ void mma16816(float* c, const uint32_t* a, const uint32_t* b) {
    asm volatile(
        "mma.sync.aligned.m16n8k16.row.col.f32.bf16.bf16.f32 "
        "{%0,%1,%2,%3}, {%4,%5,%6,%7}, {%8,%9}, {%0,%1,%2,%3};"
        : "+f"(c[0]), "+f"(c[1]), "+f"(c[2]), "+f"(c[3])
        : "r"(a[0]), "r"(a[1]), "r"(a[2]), "r"(a[3]), "r"(b[0]), "r"(b[1]));
}

// ---------------- matvec partials, fixed 16 k-chunks (<=512 active threads) ----------------
template<int NCT, int LDW, int K>
__device__ __forceinline__ void mv16(
    const float* __restrict__ src, const float* __restrict__ W,
    float* __restrict__ pp, int tid)
{
    constexpr int NCG = NCT / 4;
    constexpr int CH  = K / 16;
    if (tid < NCG * 16) {
        int cg = tid & (NCG - 1);
        int kq = tid / NCG;
        const float4* Wb = reinterpret_cast<const float4*>(W + (kq * CH) * LDW) + cg;
        const float* s = src + kq * CH;
        float4 a = make_float4(0.f, 0.f, 0.f, 0.f);
        #pragma unroll
        for (int k = 0; k < CH; k++) {
            float sv = s[k];
            float4 w = Wb[k * (LDW / 4)];
            a.x += sv * w.x; a.y += sv * w.y; a.z += sv * w.z; a.w += sv * w.w;
        }
        reinterpret_cast<float4*>(pp)[kq * NCG + cg] = a;
    }
}

// ---------------- prepB: W_proj -> plain [n][k] bf16 hi/lo tiles ----------------
__global__ void prepB_kernel(const float* __restrict__ Wp) {
    extern __shared__ unsigned short sh[];
    unsigned short* s_hi = sh;                 // [128 n][stride 136]
    unsigned short* s_lo = sh + 128 * 136;
    int nt = blockIdx.x;
    int c0 = nt * 128;
    int tid = threadIdx.x;

    for (int idx = tid; idx < 128 * 128; idx += 256) {
        int k = idx >> 7, cc = idx & 127;
        int c = c0 + cc;
        float v = (c < V) ? Wp[(long)k * V + c] : 0.f;
        __nv_bfloat16 h = __float2bfloat16(v);
        float lf = v - __bfloat162float(h);
        __nv_bfloat16 l = __float2bfloat16(lf);
        s_hi[cc * 136 + k] = *reinterpret_cast<unsigned short*>(&h);
        s_lo[cc * 136 + k] = *reinterpret_cast<unsigned short*>(&l);
    }
    __syncthreads();

    unsigned short* dh = g_Bhi + (long)nt * 16384;
    unsigned short* dl = g_Blo + (long)nt * 16384;
    for (int idx = tid; idx < 128 * 16; idx += 256) {
        int n = idx >> 4, ch = idx & 15;
        *reinterpret_cast<uint4*>(dh + n * 128 + ch * 8) =
            *reinterpret_cast<const uint4*>(s_hi + n * 136 + ch * 8);
        *reinterpret_cast<uint4*>(dl + n * 128 + ch * 8) =
            *reinterpret_cast<const uint4*>(s_lo + n * 136 + ch * 8);
    }
}

// ---------------- x-part precompute (device-side symbol resolution!) ----------------
__global__ void xpart_all_kernel(
    const int* __restrict__ x, const int* __restrict__ y,
    const float* __restrict__ emb,
    const float* __restrict__ e0_gk, const float* __restrict__ e0_gb,
    const float* __restrict__ e0_ck, const float* __restrict__ e0_cb,
    const float* __restrict__ d0_gk, const float* __restrict__ d0_gb,
    const float* __restrict__ d0_ck, const float* __restrict__ d0_cb)
{
    int which = blockIdx.y;
    float* out;
    const float* W; const float* bias; const int* ids; int ncols;
    switch (which) {
        case 0:  out = g_egx; W = e0_gk; bias = e0_gb; ids = x; ncols = 256; break;
        case 1:  out = g_ecx; W = e0_ck; bias = e0_cb; ids = x; ncols = 128; break;
        case 2:  out = g_dgx; W = d0_gk; bias = d0_gb; ids = y; ncols = 256; break;
        default: out = g_dcx; W = d0_ck; bias = d0_cb; ids = y; ncols = 128; break;
    }
    __shared__ float xs[8][E];
    int row0 = blockIdx.x * 8;
    int tid = threadIdx.x;
    for (int e = tid; e < 8 * E; e += 256) {
        int r = e / E, k = e - r * E;
        xs[r][k] = emb[(long)ids[row0 + r] * E + k];
    }
    __syncthreads();
    if (tid < ncols) {
        int j = tid;
        float acc[8];
        #pragma unroll
        for (int r = 0; r < 8; r++) acc[r] = 0.f;
        #pragma unroll 10
        for (int k = 0; k < E; k++) {
            float w = W[k * ncols + j];
            #pragma unroll
            for (int r = 0; r < 8; r++) acc[r] += xs[r][k] * w;
        }
        float bv = bias[j];
        #pragma unroll
        for (int r = 0; r < 8; r++) out[(row0 + r) * ncols + j] = acc[r] + bv;
    }
}

// ---------------- fused encoder + keys: 2-CTA cluster, 512 thr, 2 CTAs/SM ----------------
__global__ void __cluster_dims__(2, 1, 1) __launch_bounds__(512, 2) enc_fused(
    const float* __restrict__ e0_gk, const float* __restrict__ e0_ck,
    const float* __restrict__ e1_gk, const float* __restrict__ e1_gb,
    const float* __restrict__ e1_ck, const float* __restrict__ e1_cb,
    const float* __restrict__ W_mem, const int* __restrict__ x_len)
{
    int b = blockIdx.x >> 1;
    unsigned rank = ctarank_();
    unsigned peer = rank ^ 1u;
    int tid = threadIdx.x;
    int xlen = x_len[b];

    __shared__ float h0s[H], h1s[H], n0s[H], us0[H], us1[H], rh[H];
    __shared__ float cb[2 * H];
    __shared__ float pp[2048];
    __shared__ float mems[S][H];

    if (tid < H) { h0s[tid] = 0.f; h1s[tid] = 0.f; }
    cluster_sync_();

    for (int t = 0; t < S; t++) {
        bool valid = (t < xlen);
        mv16<128, 256, 128>(h0s, e0_gk + E * 256 + rank * 128, pp, tid);
        __syncthreads();
        if (tid < 128) {
            int gc = rank * 128 + tid;
            float acc = g_egx[(b * S + t) * 256 + gc];
            #pragma unroll
            for (int q = 0; q < 16; q++) acc += pp[q * 128 + tid];
            float v = sigmoid_fast(acc);
            if (rank == 0) { float rv = v * h0s[tid]; rh[tid] = rv; st_peer(&rh[tid], peer, rv); }
            else           { us0[tid] = v;            st_peer(&us0[tid], peer, v); }
        }
        cluster_sync_();
        mv16<64, 128, 128>(rh, e0_ck + E * 128 + rank * 64, pp, tid);
        __syncthreads();
        if (tid < 64) {
            int c = rank * 64 + tid;
            float acc = g_ecx[(b * S + t) * H + c];
            #pragma unroll
            for (int q = 0; q < 16; q++) acc += pp[q * 64 + tid];
            float cc = tanh_fast(acc);
            float u = us0[c];
            float n0 = u * h0s[c] + (1.f - u) * cc;
            n0s[c] = n0; st_peer(&n0s[c], peer, n0);
            cb[c] = n0;  st_peer(&cb[c], peer, n0);
        }
        if (tid < H) cb[H + tid] = h1s[tid];
        cluster_sync_();
        mv16<128, 256, 256>(cb, e1_gk + rank * 128, pp, tid);
        __syncthreads();
        if (tid < 128) {
            int gc = rank * 128 + tid;
            float acc = e1_gb[gc];
            #pragma unroll
            for (int q = 0; q < 16; q++) acc += pp[q * 128 + tid];
            float v = sigmoid_fast(acc);
            if (rank == 0) { float rv = v * h1s[tid]; cb[H + tid] = rv; st_peer(&cb[H + tid], peer, rv); }
            else           { us1[tid] = v;            st_peer(&us1[tid], peer, v); }
        }
        cluster_sync_();
        mv16<64, 128, 256>(cb, e1_ck + rank * 64, pp, tid);
        __syncthreads();
        if (tid < 64) {
            int c = rank * 64 + tid;
            float acc = e1_cb[c];
            #pragma unroll
            for (int q = 0; q < 16; q++) acc += pp[q * 64 + tid];
            float cc = tanh_fast(acc);
            float u = us1[c];
            float n1 = u * h1s[c] + (1.f - u) * cc;
            float mv;
            if (valid) {
                h1s[c] = n1; st_peer(&h1s[c], peer, n1);
                mv = n1;
            } else {
                mv = 0.f;
            }
            mems[t][c] = mv; st_peer(&mems[t][c], peer, mv);
            g_mem[(b * S + t) * H + c] = mv;
        }
        if (tid < H && valid) h0s[tid] = n0s[tid];
        cluster_sync_();
    }
    if (rank == 0 && tid < H) {
        g_h0[b * H + tid] = h0s[tid];
        g_h1[b * H + tid] = h1s[tid];
    }
    for (int idx = tid; idx < S * 64; idx += 512) {
        int t = idx >> 6, c = idx & 63;
        int gc = (int)rank * 64 + c;
        float a0 = 0.f, a1 = 0.f, a2 = 0.f, a3 = 0.f;
        #pragma unroll 8
        for (int k = 0; k < H; k += 4) {
            a0 += mems[t][k]     * W_mem[k * H + gc];
            a1 += mems[t][k + 1] * W_mem[(k + 1) * H + gc];
            a2 += mems[t][k + 2] * W_mem[(k + 2) * H + gc];
            a3 += mems[t][k + 3] * W_mem[(k + 3) * H + gc];
        }
        g_keys[(b * S + t) * H + gc] = (a0 + a1) + (a2 + a3);
    }
}

// ---------------- fused decoder: 2-CTA cluster, 512 thr, 2 CTAs/SM ----------------
__global__ void __cluster_dims__(2, 1, 1) __launch_bounds__(512, 2) dec_fused(
    const float* __restrict__ d0_gk, const float* __restrict__ d0_ck,
    const float* __restrict__ d1_gk, const float* __restrict__ d1_gb,
    const float* __restrict__ d1_ck, const float* __restrict__ d1_cb,
    const float* __restrict__ W_q, const float* __restrict__ v_att,
    const float* __restrict__ W_attn, const int* __restrict__ x_len)
{
    int b = blockIdx.x >> 1;
    unsigned rank = ctarank_();
    unsigned peer = rank ^ 1u;
    int tid = threadIdx.x;
    int xlen = x_len[b];

    __shared__ float h0s[H], h1s[H], n0s[H], n1s[H], qs[H], us0[H], us1[H];
    __shared__ float cb[2 * H];
    __shared__ float pp[2048];
    __shared__ float sco[S];

    if (tid < H) {
        float h0 = g_h0[b * H + tid];
        h0s[tid] = h0;
        h1s[tid] = g_h1[b * H + tid];
        cb[tid] = 0.f;
        cb[H + tid] = h0;
    }
    cluster_sync_();

    for (int t = 0; t < S; t++) {
        mv16<128, 256, 256>(cb, d0_gk + E * 256 + rank * 128, pp, tid);
        __syncthreads();
        if (tid < 128) {
            int gc = rank * 128 + tid;
            float acc = g_dgx[(b * S + t) * 256 + gc];
            #pragma unroll
            for (int q = 0; q < 16; q++) acc += pp[q * 128 + tid];
            float v = sigmoid_fast(acc);
            if (rank == 0) { float rv = v * h0s[tid]; cb[H + tid] = rv; st_peer(&cb[H + tid], peer, rv); }
            else           { us0[tid] = v;            st_peer(&us0[tid], peer, v); }
        }
        cluster_sync_();
        mv16<64, 128, 256>(cb, d0_ck + E * 128 + rank * 64, pp, tid);
        __syncthreads();
        if (tid < 64) {
            int c = rank * 64 + tid;
            float acc = g_dcx[(b * S + t) * H + c];
            #pragma unroll
            for (int q = 0; q < 16; q++) acc += pp[q * 64 + tid];
            float cc = tanh_fast(acc);
            float u = us0[c];
            float n0 = u * h0s[c] + (1.f - u) * cc;
            n0s[c] = n0; st_peer(&n0s[c], peer, n0);
            cb[c] = n0;  st_peer(&cb[c], peer, n0);
        }
        if (tid < H) cb[H + tid] = h1s[tid];
        cluster_sync_();
        mv16<128, 256, 256>(cb, d1_gk + rank * 128, pp, tid);
        __syncthreads();
        if (tid < 128) {
            int gc = rank * 128 + tid;
            float acc = d1_gb[gc];
            #pragma unroll
            for (int q = 0; q < 16; q++) acc += pp[q * 128 + tid];
            float v = sigmoid_fast(acc);
            if (rank == 0) { float rv = v * h1s[tid]; cb[H + tid] = rv; st_peer(&cb[H + tid], peer, rv); }
            else           { us1[tid] = v;            st_peer(&us1[tid], peer, v); }
        }
        cluster_sync_();
        mv16<64, 128, 256>(cb, d1_ck + rank * 64, pp, tid);
        __syncthreads();
        if (tid < 64) {
            int c = rank * 64 + tid;
            float acc = d1_cb[c];
            #pragma unroll
            for (int q = 0; q < 16; q++) acc += pp[q * 64 + tid];
            float cc = tanh_fast(acc);
            float u = us1[c];
            float n1 = u * h1s[c] + (1.f - u) * cc;
            n1s[c] = n1; st_peer(&n1s[c], peer, n1);
        }
        cluster_sync_();
        mv16<64, 128, 128>(n1s, W_q + rank * 64, pp, tid);
        __syncthreads();
        if (tid < 64) {
            int c = rank * 64 + tid;
            float acc = 0.f;
            #pragma unroll
            for (int q = 0; q < 16; q++) acc += pp[q * 64 + tid];
            qs[c] = acc; st_peer(&qs[c], peer, acc);
        }
        cluster_sync_();
        // attention scores: 16-lane group per source position (32 groups >= S)
        {
            int grp = tid >> 4, l16 = tid & 15;
            if (grp < S) {
                float acc = 0.f;
                const float* kr = &g_keys[(b * S + grp) * H];
                #pragma unroll
                for (int u = 0; u < 8; u++) {
                    int uu = l16 + u * 16;
                    acc += tanh_fast(kr[uu] + qs[uu]) * v_att[uu];
                }
                #pragma unroll
                for (int off = 8; off > 0; off >>= 1)
                    acc += __shfl_xor_sync(0xffffffffu, acc, off, 16);
                if (l16 == 0)
                    sco[grp] = (grp >= xlen) ? -3.4028235e38f : acc;
            }
        }
        __syncthreads();
        if (tid == 0) {
            float m = -3.4028235e38f;
            #pragma unroll
            for (int s = 0; s < S; s++) m = fmaxf(m, sco[s]);
            float sum = 0.f;
            #pragma unroll
            for (int s = 0; s < S; s++) { float ev = __expf(sco[s] - m); sco[s] = ev; sum += ev; }
            float inv = __fdividef(1.f, sum);
            #pragma unroll
            for (int s = 0; s < S; s++) sco[s] *= inv;
        }
        __syncthreads();
        if (tid < H) {
            float acc = 0.f;
            #pragma unroll
            for (int s = 0; s < S; s++) acc += sco[s] * g_mem[(b * S + s) * H + tid];
            cb[H + tid] = acc;
            cb[tid] = n1s[tid];
        }
        __syncthreads();
        mv16<64, 128, 256>(cb, W_attn + rank * 64, pp, tid);
        __syncthreads();
        if (tid < 64) {
            int c = rank * 64 + tid;
            float acc = 0.f;
            #pragma unroll
            for (int q = 0; q < 16; q++) acc += pp[q * 64 + tid];
            g_na[(b * S + t) * H + c] = acc;
            cb[c] = acc; st_peer(&cb[c], peer, acc);
        }
        if (tid < H) {
            h0s[tid] = n0s[tid];
            h1s[tid] = n1s[tid];
            cb[H + tid] = n0s[tid];
        }
        cluster_sync_();
    }
}

// ---------------- projection: mma.sync bf16 split-precision GEMM ----------------
#define PROJ_SMEM 140288

__global__ __launch_bounds__(256, 1) void proj_kernel(
    const float* __restrict__ bias, const int* __restrict__ y_len,
    float* __restrict__ out)
{
    extern __shared__ char psm[];
    float* sb = reinterpret_cast<float*>(psm);
    int* yl = reinterpret_cast<int*>(psm + 512);
    unsigned short* Ah = reinterpret_cast<unsigned short*>(psm + 1024);
    unsigned short* Al = reinterpret_cast<unsigned short*>(psm + 35840);
    unsigned short* Bh = reinterpret_cast<unsigned short*>(psm + 70656);
    unsigned short* Bl = reinterpret_cast<unsigned short*>(psm + 105472);

    int tid = threadIdx.x;
    int nt = blockIdx.x;
    int bm0 = blockIdx.y * 128;
    int c0 = nt * 128;

    {
        const uint4* shh = reinterpret_cast<const uint4*>(g_Bhi + (long)nt * 16384);
        const uint4* shl = reinterpret_cast<const uint4*>(g_Blo + (long)nt * 16384);
        #pragma unroll
        for (int i = tid; i < 2048; i += 256) {
            int n = i >> 4, ch = i & 15;
            *reinterpret_cast<uint4*>(Bh + n * 136 + ch * 8) = shh[i];
            *reinterpret_cast<uint4*>(Bl + n * 136 + ch * 8) = shl[i];
        }
    }
    {
        int r = tid >> 1, half = tid & 1;
        const float2* ar = reinterpret_cast<const float2*>(g_na + (long)(bm0 + r) * H) + half * 32;
        uint32_t* Ah32 = reinterpret_cast<uint32_t*>(Ah) + r * 68 + half * 32;
        uint32_t* Al32 = reinterpret_cast<uint32_t*>(Al) + r * 68 + half * 32;
        #pragma unroll
        for (int i = 0; i < 32; i++) {
            float2 v = ar[i];
            __nv_bfloat16 h0 = __float2bfloat16(v.x);
            __nv_bfloat16 h1 = __float2bfloat16(v.y);
            __nv_bfloat162 hp; hp.x = h0; hp.y = h1;
            __nv_bfloat162 lp;
            lp.x = __float2bfloat16(v.x - __bfloat162float(h0));
            lp.y = __float2bfloat16(v.y - __bfloat162float(h1));
            Ah32[i] = *reinterpret_cast<uint32_t*>(&hp);
            Al32[i] = *reinterpret_cast<uint32_t*>(&lp);
        }
    }
    if (tid < 128) sb[tid] = (c0 + tid < V) ? bias[c0 + tid] : 0.f;
    if (tid < 64) yl[tid] = y_len[tid];
    __syncthreads();

    int w = tid >> 5, lane = tid & 31;
    int g = lane >> 2, t4 = lane & 3;
    int r0 = w * 16;

    float acc[16][4];
    #pragma unroll
    for (int nn = 0; nn < 16; nn++)
        #pragma unroll
        for (int i = 0; i < 4; i++) acc[nn][i] = 0.f;

    #pragma unroll
    for (int kk = 0; kk < 8; kk++) {
        int k0 = kk * 16;
        const unsigned short* pah = Ah + (r0 + g) * 136 + k0 + t4 * 2;
        const unsigned short* pal = Al + (r0 + g) * 136 + k0 + t4 * 2;
        uint32_t ah[4], al[4];
        ah[0] = *reinterpret_cast<const uint32_t*>(pah);
        ah[1] = *reinterpret_cast<const uint32_t*>(pah + 8 * 136);
        ah[2] = *reinterpret_cast<const uint32_t*>(pah + 8);
        ah[3] = *reinterpret_cast<const uint32_t*>(pah + 8 * 136 + 8);
        al[0] = *reinterpret_cast<const uint32_t*>(pal);
        al[1] = *reinterpret_cast<const uint32_t*>(pal + 8 * 136);
        al[2] = *reinterpret_cast<const uint32_t*>(pal + 8);
        al[3] = *reinterpret_cast<const uint32_t*>(pal + 8 * 136 + 8);
        #pragma unroll
        for (int nn = 0; nn < 16; nn++) {
            const unsigned short* pbh = Bh + (nn * 8 + g) * 136 + k0 + t4 * 2;
            const unsigned short* pbl = Bl + (nn * 8 + g) * 136 + k0 + t4 * 2;
            uint32_t bh[2], bl[2];
            bh[0] = *reinterpret_cast<const uint32_t*>(pbh);
            bh[1] = *reinterpret_cast<const uint32_t*>(pbh + 8);
            bl[0] = *reinterpret_cast<const uint32_t*>(pbl);
            bl[1] = *reinterpret_cast<const uint32_t*>(pbl + 8);
            mma16816(acc[nn], ah, bh);
            mma16816(acc[nn], ah, bl);
            mma16816(acc[nn], al, bh);
        }
    }
    __syncthreads();

    float* Ds = reinterpret_cast<float*>(psm + 70656);
    #pragma unroll
    for (int nn = 0; nn < 16; nn++) {
        int cc = nn * 8 + t4 * 2;
        Ds[(r0 + g) * 129 + cc]     = acc[nn][0];
        Ds[(r0 + g) * 129 + cc + 1] = acc[nn][1];
        Ds[(r0 + g + 8) * 129 + cc]     = acc[nn][2];
        Ds[(r0 + g + 8) * 129 + cc + 1] = acc[nn][3];
    }
    __syncthreads();

    {
        int col = tid & 127;
        int rh = tid >> 7;
        bool colok = (c0 + col < V);
        float bv = sb[col];
        for (int r = rh * 64; r < rh * 64 + 64; r++) {
            int rg = bm0 + r;
            int bb = rg / S, tt = rg - bb * S;
            bool valid = (tt < yl[bb]);
            float val = valid ? (Ds[r * 129 + col] + bv) : 0.f;
            if (colok) out[(long)rg * V + c0 + col] = val;
        }
    }
}

// ---------------- host launch ----------------
extern "C" void kernel_launch(void* const* d_in, const int* in_sizes, int n_in,
                              void* d_out, int out_size) {
    const int*   x      = (const int*)d_in[0];
    const int*   x_len  = (const int*)d_in[1];
    const int*   y      = (const int*)d_in[2];
    const int*   y_len  = (const int*)d_in[3];
    const float* emb    = (const float*)d_in[4];
    const float* e0_gk  = (const float*)d_in[5];
    const float* e0_gb  = (const float*)d_in[6];
    const float* e0_ck  = (const float*)d_in[7];
    const float* e0_cb  = (const float*)d_in[8];
    const float* e1_gk  = (const float*)d_in[9];
    const float* e1_gb  = (const float*)d_in[10];
    const float* e1_ck  = (const float*)d_in[11];
    const float* e1_cb  = (const float*)d_in[12];
    const float* d0_gk  = (const float*)d_in[13];
    const float* d0_gb  = (const float*)d_in[14];
    const float* d0_ck  = (const float*)d_in[15];
    const float* d0_cb  = (const float*)d_in[16];
    const float* d1_gk  = (const float*)d_in[17];
    const float* d1_gb  = (const float*)d_in[18];
    const float* d1_ck  = (const float*)d_in[19];
    const float* d1_cb  = (const float*)d_in[20];
    const float* W_mem  = (const float*)d_in[21];
    const float* W_q    = (const float*)d_in[22];
    const float* v_att  = (const float*)d_in[23];
    const float* W_attn = (const float*)d_in[24];
    const float* W_proj = (const float*)d_in[25];
    const float* b_proj = (const float*)d_in[26];
    float* out = (float*)d_out;

    cudaFuncSetAttribute(prepB_kernel, cudaFuncAttributeMaxDynamicSharedMemorySize, 69632);
    cudaFuncSetAttribute(proj_kernel, cudaFuncAttributeMaxDynamicSharedMemorySize, PROJ_SMEM);

    prepB_kernel<<<NTILES, 256, 69632>>>(W_proj);                                    // 1
    xpart_all_kernel<<<dim3((B * S) / 8, 4), 256>>>(
        x, y, emb, e0_gk, e0_gb, e0_ck, e0_cb, d0_gk, d0_gb, d0_ck, d0_cb);          // 2
    enc_fused<<<2 * B, 512>>>(e0_gk, e0_ck, e1_gk, e1_gb, e1_ck, e1_cb,
                              W_mem, x_len);                                         // 3
    dec_fused<<<2 * B, 512>>>(d0_gk, d0_ck, d1_gk, d1_gb, d1_ck, d1_cb,
                              W_q, v_att, W_attn, x_len);                            // 4 <- profiled
    proj_kernel<<<dim3(NTILES, (B * S) / 128), 256, PROJ_SMEM>>>(b_proj, y_len, out); // 5
}

// round 17
// speedup vs baseline: 1.0735x; 1.0735x over previous
#include <cuda_runtime.h>
#include <cuda_bf16.h>
#include <math.h>
#include <stdint.h>

#define B 64
#define S 20
#define H 128
#define E 300
#define V 50257
#define VP 50304   // V padded to multiple of 128
#define NTILES (VP / 128)   // 393
#define KP 384     // E padded to 3 chunks of 128

// ---------------- device scratch (static, no runtime alloc) ----------------
__device__ float g_h0[B * H];
__device__ float g_h1[B * H];
__device__ float g_mem[B * S * H];
__device__ float g_keys[B * S * H];
__device__ float g_egx[B * S * 2 * H];
__device__ float g_ecx[B * S * H];
__device__ float g_dgx[B * S * 2 * H];
__device__ float g_dcx[B * S * H];
__device__ float g_na[B * S * H];
// plain [n][k] bf16 hi/lo W_proj tiles (32KB per tile each)
__device__ unsigned short g_Bhi[NTILES * 16384];
__device__ unsigned short g_Blo[NTILES * 16384];
// plain [n][k] bf16 hi/lo x-part weight tiles: 6 tiles x 128 n x KP k
__device__ unsigned short g_Wxh[6 * 128 * KP];
__device__ unsigned short g_Wxl[6 * 128 * KP];

// ---------------- fast activations ----------------
__device__ __forceinline__ float tanh_fast(float x) {
    float y; asm("tanh.approx.f32 %0, %1;" : "=f"(y) : "f"(x)); return y;
}
__device__ __forceinline__ float sigmoid_fast(float x) {
    return fmaf(0.5f, tanh_fast(0.5f * x), 0.5f);
}

// ---------------- cluster helpers ----------------
__device__ __forceinline__ unsigned ctarank_() {
    unsigned r; asm("mov.u32 %0, %%cluster_ctarank;" : "=r"(r)); return r;
}
__device__ __forceinline__ void cluster_sync_() {
    asm volatile("barrier.cluster.arrive.aligned;" ::: "memory");
    asm volatile("barrier.cluster.wait.aligned;" ::: "memory");
}
__device__ __forceinline__ void st_peer(float* p, unsigned peer, float v) {
    unsigned la = (unsigned)__cvta_generic_to_shared(p);
    unsigned ra;
    asm("mapa.shared::cluster.u32 %0, %1, %2;" : "=r"(ra) : "r"(la), "r"(peer));
    asm volatile("st.shared::cluster.f32 [%0], %1;" :: "r"(ra), "f"(v));
}

// ---------------- warp-level bf16 MMA (sm_80+ HMMA; works on plain sm_103) ----------------
__device__ __forceinline__ void mma16816(float* c, const uint32_t* a, const uint32_t* b) {
    asm volatile(
        "mma.sync.aligned.m16n8k16.row.col.f32.bf16.bf16.f32 "
        "{%0,%1,%2,%3}, {%4,%5,%6,%7}, {%8,%9}, {%0,%1,%2,%3};"
        : "+f"(c[0]), "+f"(c[1]), "+f"(c[2]), "+f"(c[3])
        : "r"(a[0]), "r"(a[1]), "r"(a[2]), "r"(a[3]), "r"(b[0]), "r"(b[1]));
}

// ---------------- matvec partials, fixed 16 k-chunks ----------------
template<int NCT, int LDW, int K>
__device__ __forceinline__ void mv16(
    const float* __restrict__ src, const float* __restrict__ W,
    float* __restrict__ pp, int tid)
{
    constexpr int NCG = NCT / 4;
    constexpr int CH  = K / 16;
    if (tid < NCG * 16) {
        int cg = tid & (NCG - 1);
        int kq = tid / NCG;
        const float4* Wb = reinterpret_cast<const float4*>(W + (kq * CH) * LDW) + cg;
        const float* s = src + kq * CH;
        float4 a = make_float4(0.f, 0.f, 0.f, 0.f);
        #pragma unroll
        for (int k = 0; k < CH; k++) {
            float sv = s[k];
            float4 w = Wb[k * (LDW / 4)];
            a.x += sv * w.x; a.y += sv * w.y; a.z += sv * w.z; a.w += sv * w.w;
        }
        reinterpret_cast<float4*>(pp)[kq * NCG + cg] = a;
    }
}

// ---------------- prepB: W_proj -> plain [n][k] bf16 hi/lo tiles ----------------
__global__ void prepB_kernel(const float* __restrict__ Wp) {
    extern __shared__ unsigned short sh[];
    unsigned short* s_hi = sh;                 // [128 n][stride 136]
    unsigned short* s_lo = sh + 128 * 136;
    int nt = blockIdx.x;
    int c0 = nt * 128;
    int tid = threadIdx.x;

    for (int idx = tid; idx < 128 * 128; idx += 256) {
        int k = idx >> 7, cc = idx & 127;
        int c = c0 + cc;
        float v = (c < V) ? Wp[(long)k * V + c] : 0.f;
        __nv_bfloat16 h = __float2bfloat16(v);
        float lf = v - __bfloat162float(h);
        __nv_bfloat16 l = __float2bfloat16(lf);
        s_hi[cc * 136 + k] = *reinterpret_cast<unsigned short*>(&h);
        s_lo[cc * 136 + k] = *reinterpret_cast<unsigned short*>(&l);
    }
    __syncthreads();

    unsigned short* dh = g_Bhi + (long)nt * 16384;
    unsigned short* dl = g_Blo + (long)nt * 16384;
    for (int idx = tid; idx < 128 * 16; idx += 256) {
        int n = idx >> 4, ch = idx & 15;
        *reinterpret_cast<uint4*>(dh + n * 128 + ch * 8) =
            *reinterpret_cast<const uint4*>(s_hi + n * 136 + ch * 8);
        *reinterpret_cast<uint4*>(dl + n * 128 + ch * 8) =
            *reinterpret_cast<const uint4*>(s_lo + n * 136 + ch * 8);
    }
}

// ---------------- prepWx: x-part weights -> [n][KP] bf16 hi/lo tiles ----------------
// grid (6, 3): nt x k-chunk. Tile nt covers rows k<E of the weight, cols [coff, +128).
__global__ void prepWx_kernel(
    const float* __restrict__ e0_gk, const float* __restrict__ e0_ck,
    const float* __restrict__ d0_gk, const float* __restrict__ d0_ck)
{
    extern __shared__ unsigned short sh[];
    unsigned short* s_hi = sh;                 // [128 n][136]
    unsigned short* s_lo = sh + 128 * 136;
    int nt = blockIdx.x;
    int kc = blockIdx.y;
    const float* W; int ldw, coff;
    switch (nt) {
        case 0: W = e0_gk; ldw = 256; coff = 0;   break;
        case 1: W = e0_gk; ldw = 256; coff = 128; break;
        case 2: W = e0_ck; ldw = 128; coff = 0;   break;
        case 3: W = d0_gk; ldw = 256; coff = 0;   break;
        case 4: W = d0_gk; ldw = 256; coff = 128; break;
        default: W = d0_ck; ldw = 128; coff = 0;  break;
    }
    int tid = threadIdx.x;
    for (int idx = tid; idx < 128 * 128; idx += 256) {
        int k = idx >> 7, n = idx & 127;
        int kg = kc * 128 + k;
        float v = (kg < E) ? W[kg * ldw + coff + n] : 0.f;
        __nv_bfloat16 h = __float2bfloat16(v);
        float lf = v - __bfloat162float(h);
        __nv_bfloat16 l = __float2bfloat16(lf);
        s_hi[n * 136 + k] = *reinterpret_cast<unsigned short*>(&h);
        s_lo[n * 136 + k] = *reinterpret_cast<unsigned short*>(&l);
    }
    __syncthreads();
    for (int idx = tid; idx < 128 * 16; idx += 256) {
        int n = idx >> 4, ch = idx & 15;
        long dst = ((long)nt * 128 + n) * KP + kc * 128 + ch * 8;
        *reinterpret_cast<uint4*>(g_Wxh + dst) =
            *reinterpret_cast<const uint4*>(s_hi + n * 136 + ch * 8);
        *reinterpret_cast<uint4*>(g_Wxl + dst) =
            *reinterpret_cast<const uint4*>(s_lo + n * 136 + ch * 8);
    }
}

// ---------------- xgemm: x-part precompute as split-bf16 tensor GEMM ----------------
// grid (6, 10), 256 threads. M=128 rows x N=128 cols, K=KP (3 chunks of 128).
// out[row, coff+col] = emb[ids[row]] @ W + bias  (device-side symbol resolution)
#define XG_SMEM 140288

__global__ __launch_bounds__(256, 1) void xgemm_kernel(
    const int* __restrict__ x, const int* __restrict__ y,
    const float* __restrict__ emb,
    const float* __restrict__ e0_gb, const float* __restrict__ e0_cb,
    const float* __restrict__ d0_gb, const float* __restrict__ d0_cb)
{
    extern __shared__ char psm[];
    float* sb = reinterpret_cast<float*>(psm);
    unsigned short* Ah = reinterpret_cast<unsigned short*>(psm + 1024);
    unsigned short* Al = reinterpret_cast<unsigned short*>(psm + 35840);
    unsigned short* Bh = reinterpret_cast<unsigned short*>(psm + 70656);
    unsigned short* Bl = reinterpret_cast<unsigned short*>(psm + 105472);

    int nt = blockIdx.x;
    int bm0 = blockIdx.y * 128;
    int tid = threadIdx.x;

    float* outp; const float* bias; const int* ids; int ldo, coff;
    switch (nt) {
        case 0:  outp = g_egx; bias = e0_gb;       ids = x; ldo = 256; coff = 0;   break;
        case 1:  outp = g_egx; bias = e0_gb + 128; ids = x; ldo = 256; coff = 128; break;
        case 2:  outp = g_ecx; bias = e0_cb;       ids = x; ldo = 128; coff = 0;   break;
        case 3:  outp = g_dgx; bias = d0_gb;       ids = y; ldo = 256; coff = 0;   break;
        case 4:  outp = g_dgx; bias = d0_gb + 128; ids = y; ldo = 256; coff = 128; break;
        default: outp = g_dcx; bias = d0_cb;       ids = y; ldo = 128; coff = 0;   break;
    }
    if (tid < 128) sb[tid] = bias[tid];

    int w = tid >> 5, lane = tid & 31;
    int g = lane >> 2, t4 = lane & 3;
    int r0 = w * 16;

    float acc[16][4];
    #pragma unroll
    for (int nn = 0; nn < 16; nn++)
        #pragma unroll
        for (int i = 0; i < 4; i++) acc[nn][i] = 0.f;

    int ar_row = tid >> 1, ar_half = tid & 1;
    int ar_id = ids[bm0 + ar_row];
    const float* ar_base = emb + (long)ar_id * E;

    for (int kc = 0; kc < 3; kc++) {
        // stage B chunk
        {
            const uint4* shh = reinterpret_cast<const uint4*>(g_Wxh + (long)nt * 128 * KP);
            const uint4* shl = reinterpret_cast<const uint4*>(g_Wxl + (long)nt * 128 * KP);
            #pragma unroll
            for (int i = tid; i < 2048; i += 256) {
                int n = i >> 4, ch = i & 15;
                *reinterpret_cast<uint4*>(Bh + n * 136 + ch * 8) = shh[n * (KP / 8) + kc * 16 + ch];
                *reinterpret_cast<uint4*>(Bl + n * 136 + ch * 8) = shl[n * (KP / 8) + kc * 16 + ch];
            }
        }
        // stage A chunk: gather from embedding, bf16 hi/lo split; zero beyond E
        {
            uint32_t* Ah32 = reinterpret_cast<uint32_t*>(Ah) + ar_row * 68 + ar_half * 32;
            uint32_t* Al32 = reinterpret_cast<uint32_t*>(Al) + ar_row * 68 + ar_half * 32;
            int kbase = kc * 128 + ar_half * 64;
            #pragma unroll
            for (int i = 0; i < 32; i++) {
                int kg = kbase + 2 * i;
                float2 v = make_float2(0.f, 0.f);
                if (kg < E) v = *reinterpret_cast<const float2*>(ar_base + kg);
                __nv_bfloat16 h0 = __float2bfloat16(v.x);
                __nv_bfloat16 h1 = __float2bfloat16(v.y);
                __nv_bfloat162 hp; hp.x = h0; hp.y = h1;
                __nv_bfloat162 lp;
                lp.x = __float2bfloat16(v.x - __bfloat162float(h0));
                lp.y = __float2bfloat16(v.y - __bfloat162float(h1));
                Ah32[i] = *reinterpret_cast<uint32_t*>(&hp);
                Al32[i] = *reinterpret_cast<uint32_t*>(&lp);
            }
        }
        __syncthreads();

        #pragma unroll
        for (int kk = 0; kk < 8; kk++) {
            int k0 = kk * 16;
            const unsigned short* pah = Ah + (r0 + g) * 136 + k0 + t4 * 2;
            const unsigned short* pal = Al + (r0 + g) * 136 + k0 + t4 * 2;
            uint32_t ah[4], al[4];
            ah[0] = *reinterpret_cast<const uint32_t*>(pah);
            ah[1] = *reinterpret_cast<const uint32_t*>(pah + 8 * 136);
            ah[2] = *reinterpret_cast<const uint32_t*>(pah + 8);
            ah[3] = *reinterpret_cast<const uint32_t*>(pah + 8 * 136 + 8);
            al[0] = *reinterpret_cast<const uint32_t*>(pal);
            al[1] = *reinterpret_cast<const uint32_t*>(pal + 8 * 136);
            al[2] = *reinterpret_cast<const uint32_t*>(pal + 8);
            al[3] = *reinterpret_cast<const uint32_t*>(pal + 8 * 136 + 8);
            #pragma unroll
            for (int nn = 0; nn < 16; nn++) {
                const unsigned short* pbh = Bh + (nn * 8 + g) * 136 + k0 + t4 * 2;
                const unsigned short* pbl = Bl + (nn * 8 + g) * 136 + k0 + t4 * 2;
                uint32_t bh[2], bl[2];
                bh[0] = *reinterpret_cast<const uint32_t*>(pbh);
                bh[1] = *reinterpret_cast<const uint32_t*>(pbh + 8);
                bl[0] = *reinterpret_cast<const uint32_t*>(pbl);
                bl[1] = *reinterpret_cast<const uint32_t*>(pbl + 8);
                mma16816(acc[nn], ah, bh);
                mma16816(acc[nn], ah, bl);
                mma16816(acc[nn], al, bh);
            }
        }
        __syncthreads();   // done with this chunk's smem before restaging
    }

    // epilogue: stage D (reuse B area), coalesced write + bias
    float* Ds = reinterpret_cast<float*>(psm + 70656);
    #pragma unroll
    for (int nn = 0; nn < 16; nn++) {
        int cc = nn * 8 + t4 * 2;
        Ds[(r0 + g) * 129 + cc]     = acc[nn][0];
        Ds[(r0 + g) * 129 + cc + 1] = acc[nn][1];
        Ds[(r0 + g + 8) * 129 + cc]     = acc[nn][2];
        Ds[(r0 + g + 8) * 129 + cc + 1] = acc[nn][3];
    }
    __syncthreads();
    {
        int col = tid & 127;
        int rh = tid >> 7;
        float bv = sb[col];
        for (int r = rh * 64; r < rh * 64 + 64; r++) {
            outp[(bm0 + r) * ldo + coff + col] = Ds[r * 129 + col] + bv;
        }
    }
}

// ---------------- fused encoder + keys: 2-CTA cluster per batch element ----------------
__global__ void __cluster_dims__(2, 1, 1) __launch_bounds__(1024, 1) enc_fused(
    const float* __restrict__ e0_gk, const float* __restrict__ e0_ck,
    const float* __restrict__ e1_gk, const float* __restrict__ e1_gb,
    const float* __restrict__ e1_ck, const float* __restrict__ e1_cb,
    const float* __restrict__ W_mem, const int* __restrict__ x_len)
{
    int b = blockIdx.x >> 1;
    unsigned rank = ctarank_();
    unsigned peer = rank ^ 1u;
    int tid = threadIdx.x;
    int xlen = x_len[b];

    __shared__ float h0s[H], h1s[H], n0s[H], us0[H], us1[H], rh[H];
    __shared__ float cb[2 * H];
    __shared__ float pp[2048];
    __shared__ float mems[S][H];

    if (tid < H) { h0s[tid] = 0.f; h1s[tid] = 0.f; }
    cluster_sync_();

    for (int t = 0; t < S; t++) {
        bool valid = (t < xlen);
        mv16<128, 256, 128>(h0s, e0_gk + E * 256 + rank * 128, pp, tid);
        __syncthreads();
        if (tid < 128) {
            int gc = rank * 128 + tid;
            float acc = g_egx[(b * S + t) * 256 + gc];
            #pragma unroll
            for (int q = 0; q < 16; q++) acc += pp[q * 128 + tid];
            float v = sigmoid_fast(acc);
            if (rank == 0) { float rv = v * h0s[tid]; rh[tid] = rv; st_peer(&rh[tid], peer, rv); }
            else           { us0[tid] = v;            st_peer(&us0[tid], peer, v); }
        }
        cluster_sync_();
        mv16<64, 128, 128>(rh, e0_ck + E * 128 + rank * 64, pp, tid);
        __syncthreads();
        if (tid < 64) {
            int c = rank * 64 + tid;
            float acc = g_ecx[(b * S + t) * H + c];
            #pragma unroll
            for (int q = 0; q < 16; q++) acc += pp[q * 64 + tid];
            float cc = tanh_fast(acc);
            float u = us0[c];
            float n0 = u * h0s[c] + (1.f - u) * cc;
            n0s[c] = n0; st_peer(&n0s[c], peer, n0);
            cb[c] = n0;  st_peer(&cb[c], peer, n0);
        }
        if (tid < H) cb[H + tid] = h1s[tid];
        cluster_sync_();
        mv16<128, 256, 256>(cb, e1_gk + rank * 128, pp, tid);
        __syncthreads();
        if (tid < 128) {
            int gc = rank * 128 + tid;
            float acc = e1_gb[gc];
            #pragma unroll
            for (int q = 0; q < 16; q++) acc += pp[q * 128 + tid];
            float v = sigmoid_fast(acc);
            if (rank == 0) { float rv = v * h1s[tid]; cb[H + tid] = rv; st_peer(&cb[H + tid], peer, rv); }
            else           { us1[tid] = v;            st_peer(&us1[tid], peer, v); }
        }
        cluster_sync_();
        mv16<64, 128, 256>(cb, e1_ck + rank * 64, pp, tid);
        __syncthreads();
        if (tid < 64) {
            int c = rank * 64 + tid;
            float acc = e1_cb[c];
            #pragma unroll
            for (int q = 0; q < 16; q++) acc += pp[q * 64 + tid];
            float cc = tanh_fast(acc);
            float u = us1[c];
            float n1 = u * h1s[c] + (1.f - u) * cc;
            float mv;
            if (valid) {
                h1s[c] = n1; st_peer(&h1s[c], peer, n1);
                mv = n1;
            } else {
                mv = 0.f;
            }
            mems[t][c] = mv; st_peer(&mems[t][c], peer, mv);
            g_mem[(b * S + t) * H + c] = mv;
        }
        if (tid < H && valid) h0s[tid] = n0s[tid];
        cluster_sync_();
    }
    if (rank == 0 && tid < H) {
        g_h0[b * H + tid] = h0s[tid];
        g_h1[b * H + tid] = h1s[tid];
    }
    for (int idx = tid; idx < S * 64; idx += 1024) {
        int t = idx >> 6, c = idx & 63;
        int gc = (int)rank * 64 + c;
        float a0 = 0.f, a1 = 0.f, a2 = 0.f, a3 = 0.f;
        #pragma unroll 8
        for (int k = 0; k < H; k += 4) {
            a0 += mems[t][k]     * W_mem[k * H + gc];
            a1 += mems[t][k + 1] * W_mem[(k + 1) * H + gc];
            a2 += mems[t][k + 2] * W_mem[(k + 2) * H + gc];
            a3 += mems[t][k + 3] * W_mem[(k + 3) * H + gc];
        }
        g_keys[(b * S + t) * H + gc] = (a0 + a1) + (a2 + a3);
    }
}

// ---------------- fused decoder: 2-CTA cluster per batch element ----------------
__global__ void __cluster_dims__(2, 1, 1) __launch_bounds__(1024, 1) dec_fused(
    const float* __restrict__ d0_gk, const float* __restrict__ d0_ck,
    const float* __restrict__ d1_gk, const float* __restrict__ d1_gb,
    const float* __restrict__ d1_ck, const float* __restrict__ d1_cb,
    const float* __restrict__ W_q, const float* __restrict__ v_att,
    const float* __restrict__ W_attn, const int* __restrict__ x_len)
{
    int b = blockIdx.x >> 1;
    unsigned rank = ctarank_();
    unsigned peer = rank ^ 1u;
    int tid = threadIdx.x;
    int lid = tid & 31;
    int wid = tid >> 5;
    int xlen = x_len[b];

    __shared__ float h0s[H], h1s[H], n0s[H], n1s[H], qs[H], us0[H], us1[H];
    __shared__ float cb[2 * H];
    __shared__ float pp[2048];
    __shared__ float sco[S];

    if (tid < H) {
        float h0 = g_h0[b * H + tid];
        h0s[tid] = h0;
        h1s[tid] = g_h1[b * H + tid];
        cb[tid] = 0.f;
        cb[H + tid] = h0;
    }
    cluster_sync_();

    for (int t = 0; t < S; t++) {
        mv16<128, 256, 256>(cb, d0_gk + E * 256 + rank * 128, pp, tid);
        __syncthreads();
        if (tid < 128) {
            int gc = rank * 128 + tid;
            float acc = g_dgx[(b * S + t) * 256 + gc];
            #pragma unroll
            for (int q = 0; q < 16; q++) acc += pp[q * 128 + tid];
            float v = sigmoid_fast(acc);
            if (rank == 0) { float rv = v * h0s[tid]; cb[H + tid] = rv; st_peer(&cb[H + tid], peer, rv); }
            else           { us0[tid] = v;            st_peer(&us0[tid], peer, v); }
        }
        cluster_sync_();
        mv16<64, 128, 256>(cb, d0_ck + E * 128 + rank * 64, pp, tid);
        __syncthreads();
        if (tid < 64) {
            int c = rank * 64 + tid;
            float acc = g_dcx[(b * S + t) * H + c];
            #pragma unroll
            for (int q = 0; q < 16; q++) acc += pp[q * 64 + tid];
            float cc = tanh_fast(acc);
            float u = us0[c];
            float n0 = u * h0s[c] + (1.f - u) * cc;
            n0s[c] = n0; st_peer(&n0s[c], peer, n0);
            cb[c] = n0;  st_peer(&cb[c], peer, n0);
        }
        if (tid < H) cb[H + tid] = h1s[tid];
        cluster_sync_();
        mv16<128, 256, 256>(cb, d1_gk + rank * 128, pp, tid);
        __syncthreads();
        if (tid < 128) {
            int gc = rank * 128 + tid;
            float acc = d1_gb[gc];
            #pragma unroll
            for (int q = 0; q < 16; q++) acc += pp[q * 128 + tid];
            float v = sigmoid_fast(acc);
            if (rank == 0) { float rv = v * h1s[tid]; cb[H + tid] = rv; st_peer(&cb[H + tid], peer, rv); }
            else           { us1[tid] = v;            st_peer(&us1[tid], peer, v); }
        }
        cluster_sync_();
        mv16<64, 128, 256>(cb, d1_ck + rank * 64, pp, tid);
        __syncthreads();
        if (tid < 64) {
            int c = rank * 64 + tid;
            float acc = d1_cb[c];
            #pragma unroll
            for (int q = 0; q < 16; q++) acc += pp[q * 64 + tid];
            float cc = tanh_fast(acc);
            float u = us1[c];
            float n1 = u * h1s[c] + (1.f - u) * cc;
            n1s[c] = n1; st_peer(&n1s[c], peer, n1);
        }
        cluster_sync_();
        mv16<64, 128, 128>(n1s, W_q + rank * 64, pp, tid);
        __syncthreads();
        if (tid < 64) {
            int c = rank * 64 + tid;
            float acc = 0.f;
            #pragma unroll
            for (int q = 0; q < 16; q++) acc += pp[q * 64 + tid];
            qs[c] = acc; st_peer(&qs[c], peer, acc);
        }
        cluster_sync_();
        if (wid < S) {
            int s = wid;
            float acc = 0.f;
            const float* kr = &g_keys[(b * S + s) * H];
            #pragma unroll
            for (int u = 0; u < 4; u++) {
                int uu = lid + u * 32;
                acc += tanh_fast(kr[uu] + qs[uu]) * v_att[uu];
            }
            #pragma unroll
            for (int off = 16; off > 0; off >>= 1)
                acc += __shfl_xor_sync(0xffffffffu, acc, off);
            if (lid == 0)
                sco[s] = (s >= xlen) ? -3.4028235e38f : acc;
        }
        __syncthreads();
        if (tid == 0) {
            float m = -3.4028235e38f;
            #pragma unroll
            for (int s = 0; s < S; s++) m = fmaxf(m, sco[s]);
            float sum = 0.f;
            #pragma unroll
            for (int s = 0; s < S; s++) { float ev = __expf(sco[s] - m); sco[s] = ev; sum += ev; }
            float inv = __fdividef(1.f, sum);
            #pragma unroll
            for (int s = 0; s < S; s++) sco[s] *= inv;
        }
        __syncthreads();
        if (tid < H) {
            float acc = 0.f;
            #pragma unroll
            for (int s = 0; s < S; s++) acc += sco[s] * g_mem[(b * S + s) * H + tid];
            cb[H + tid] = acc;
            cb[tid] = n1s[tid];
        }
        __syncthreads();
        mv16<64, 128, 256>(cb, W_attn + rank * 64, pp, tid);
        __syncthreads();
        if (tid < 64) {
            int c = rank * 64 + tid;
            float acc = 0.f;
            #pragma unroll
            for (int q = 0; q < 16; q++) acc += pp[q * 64 + tid];
            g_na[(b * S + t) * H + c] = acc;
            cb[c] = acc; st_peer(&cb[c], peer, acc);
        }
        if (tid < H) {
            h0s[tid] = n0s[tid];
            h1s[tid] = n1s[tid];
            cb[H + tid] = n0s[tid];
        }
        cluster_sync_();
    }
}

// ---------------- projection: mma.sync bf16 split-precision GEMM ----------------
#define PROJ_SMEM 140288

__global__ __launch_bounds__(256, 1) void proj_kernel(
    const float* __restrict__ bias, const int* __restrict__ y_len,
    float* __restrict__ out)
{
    extern __shared__ char psm[];
    float* sb = reinterpret_cast<float*>(psm);
    int* yl = reinterpret_cast<int*>(psm + 512);
    unsigned short* Ah = reinterpret_cast<unsigned short*>(psm + 1024);
    unsigned short* Al = reinterpret_cast<unsigned short*>(psm + 35840);
    unsigned short* Bh = reinterpret_cast<unsigned short*>(psm + 70656);
    unsigned short* Bl = reinterpret_cast<unsigned short*>(psm + 105472);

    int tid = threadIdx.x;
    int nt = blockIdx.x;
    int bm0 = blockIdx.y * 128;
    int c0 = nt * 128;

    {
        const uint4* shh = reinterpret_cast<const uint4*>(g_Bhi + (long)nt * 16384);
        const uint4* shl = reinterpret_cast<const uint4*>(g_Blo + (long)nt * 16384);
        #pragma unroll
        for (int i = tid; i < 2048; i += 256) {
            int n = i >> 4, ch = i & 15;
            *reinterpret_cast<uint4*>(Bh + n * 136 + ch * 8) = shh[i];
            *reinterpret_cast<uint4*>(Bl + n * 136 + ch * 8) = shl[i];
        }
    }
    {
        int r = tid >> 1, half = tid & 1;
        const float2* ar = reinterpret_cast<const float2*>(g_na + (long)(bm0 + r) * H) + half * 32;
        uint32_t* Ah32 = reinterpret_cast<uint32_t*>(Ah) + r * 68 + half * 32;
        uint32_t* Al32 = reinterpret_cast<uint32_t*>(Al) + r * 68 + half * 32;
        #pragma unroll
        for (int i = 0; i < 32; i++) {
            float2 v = ar[i];
            __nv_bfloat16 h0 = __float2bfloat16(v.x);
            __nv_bfloat16 h1 = __float2bfloat16(v.y);
            __nv_bfloat162 hp; hp.x = h0; hp.y = h1;
            __nv_bfloat162 lp;
            lp.x = __float2bfloat16(v.x - __bfloat162float(h0));
            lp.y = __float2bfloat16(v.y - __bfloat162float(h1));
            Ah32[i] = *reinterpret_cast<uint32_t*>(&hp);
            Al32[i] = *reinterpret_cast<uint32_t*>(&lp);
        }
    }
    if (tid < 128) sb[tid] = (c0 + tid < V) ? bias[c0 + tid] : 0.f;
    if (tid < 64) yl[tid] = y_len[tid];
    __syncthreads();

    int w = tid >> 5, lane = tid & 31;
    int g = lane >> 2, t4 = lane & 3;
    int r0 = w * 16;

    float acc[16][4];
    #pragma unroll
    for (int nn = 0; nn < 16; nn++)
        #pragma unroll
        for (int i = 0; i < 4; i++) acc[nn][i] = 0.f;

    #pragma unroll
    for (int kk = 0; kk < 8; kk++) {
        int k0 = kk * 16;
        const unsigned short* pah = Ah + (r0 + g) * 136 + k0 + t4 * 2;
        const unsigned short* pal = Al + (r0 + g) * 136 + k0 + t4 * 2;
        uint32_t ah[4], al[4];
        ah[0] = *reinterpret_cast<const uint32_t*>(pah);
        ah[1] = *reinterpret_cast<const uint32_t*>(pah + 8 * 136);
        ah[2] = *reinterpret_cast<const uint32_t*>(pah + 8);
        ah[3] = *reinterpret_cast<const uint32_t*>(pah + 8 * 136 + 8);
        al[0] = *reinterpret_cast<const uint32_t*>(pal);
        al[1] = *reinterpret_cast<const uint32_t*>(pal + 8 * 136);
        al[2] = *reinterpret_cast<const uint32_t*>(pal + 8);
        al[3] = *reinterpret_cast<const uint32_t*>(pal + 8 * 136 + 8);
        #pragma unroll
        for (int nn = 0; nn < 16; nn++) {
            const unsigned short* pbh = Bh + (nn * 8 + g) * 136 + k0 + t4 * 2;
            const unsigned short* pbl = Bl + (nn * 8 + g) * 136 + k0 + t4 * 2;
            uint32_t bh[2], bl[2];
            bh[0] = *reinterpret_cast<const uint32_t*>(pbh);
            bh[1] = *reinterpret_cast<const uint32_t*>(pbh + 8);
            bl[0] = *reinterpret_cast<const uint32_t*>(pbl);
            bl[1] = *reinterpret_cast<const uint32_t*>(pbl + 8);
            mma16816(acc[nn], ah, bh);
            mma16816(acc[nn], ah, bl);
            mma16816(acc[nn], al, bh);
        }
    }
    __syncthreads();

    float* Ds = reinterpret_cast<float*>(psm + 70656);
    #pragma unroll
    for (int nn = 0; nn < 16; nn++) {
        int cc = nn * 8 + t4 * 2;
        Ds[(r0 + g) * 129 + cc]     = acc[nn][0];
        Ds[(r0 + g) * 129 + cc + 1] = acc[nn][1];
        Ds[(r0 + g + 8) * 129 + cc]     = acc[nn][2];
        Ds[(r0 + g + 8) * 129 + cc + 1] = acc[nn][3];
    }
    __syncthreads();

    {
        int col = tid & 127;
        int rh = tid >> 7;
        bool colok = (c0 + col < V);
        float bv = sb[col];
        for (int r = rh * 64; r < rh * 64 + 64; r++) {
            int rg = bm0 + r;
            int bb = rg / S, tt = rg - bb * S;
            bool valid = (tt < yl[bb]);
            float val = valid ? (Ds[r * 129 + col] + bv) : 0.f;
            if (colok) out[(long)rg * V + c0 + col] = val;
        }
    }
}

// ---------------- host launch ----------------
extern "C" void kernel_launch(void* const* d_in, const int* in_sizes, int n_in,
                              void* d_out, int out_size) {
    const int*   x      = (const int*)d_in[0];
    const int*   x_len  = (const int*)d_in[1];
    const int*   y      = (const int*)d_in[2];
    const int*   y_len  = (const int*)d_in[3];
    const float* emb    = (const float*)d_in[4];
    const float* e0_gk  = (const float*)d_in[5];
    const float* e0_gb  = (const float*)d_in[6];
    const float* e0_ck  = (const float*)d_in[7];
    const float* e0_cb  = (const float*)d_in[8];
    const float* e1_gk  = (const float*)d_in[9];
    const float* e1_gb  = (const float*)d_in[10];
    const float* e1_ck  = (const float*)d_in[11];
    const float* e1_cb  = (const float*)d_in[12];
    const float* d0_gk  = (const float*)d_in[13];
    const float* d0_gb  = (const float*)d_in[14];
    const float* d0_ck  = (const float*)d_in[15];
    const float* d0_cb  = (const float*)d_in[16];
    const float* d1_gk  = (const float*)d_in[17];
    const float* d1_gb  = (const float*)d_in[18];
    const float* d1_ck  = (const float*)d_in[19];
    const float* d1_cb  = (const float*)d_in[20];
    const float* W_mem  = (const float*)d_in[21];
    const float* W_q    = (const float*)d_in[22];
    const float* v_att  = (const float*)d_in[23];
    const float* W_attn = (const float*)d_in[24];
    const float* W_proj = (const float*)d_in[25];
    const float* b_proj = (const float*)d_in[26];
    float* out = (float*)d_out;

    cudaFuncSetAttribute(prepB_kernel, cudaFuncAttributeMaxDynamicSharedMemorySize, 69632);
    cudaFuncSetAttribute(prepWx_kernel, cudaFuncAttributeMaxDynamicSharedMemorySize, 69632);
    cudaFuncSetAttribute(xgemm_kernel, cudaFuncAttributeMaxDynamicSharedMemorySize, XG_SMEM);
    cudaFuncSetAttribute(proj_kernel, cudaFuncAttributeMaxDynamicSharedMemorySize, PROJ_SMEM);

    prepB_kernel<<<NTILES, 256, 69632>>>(W_proj);                                    // 1
    prepWx_kernel<<<dim3(6, 3), 256, 69632>>>(e0_gk, e0_ck, d0_gk, d0_ck);           // 2
    xgemm_kernel<<<dim3(6, 10), 256, XG_SMEM>>>(x, y, emb,
                                                e0_gb, e0_cb, d0_gb, d0_cb);         // 3
    enc_fused<<<2 * B, 1024>>>(e0_gk, e0_ck, e1_gk, e1_gb, e1_ck, e1_cb,
                               W_mem, x_len);                                        // 4 <- profiled
    dec_fused<<<2 * B, 1024>>>(d0_gk, d0_ck, d1_gk, d1_gb, d1_ck, d1_cb,
                               W_q, v_att, W_attn, x_len);                           // 5
    proj_kernel<<<dim3(NTILES, (B * S) / 128), 256, PROJ_SMEM>>>(b_proj, y_len, out); // 6
}